// round 17
// baseline (speedup 1.0000x reference)
#include <cuda_runtime.h>
#include <cstdint>

// WeightedRuleLayer: out[r,:] = tanh( sum_p layer_values[idx[r,p],:] * weights[r,p,:] )
// D=128, P=8.
//
// Byte ledger is pinned at ~1.59GB (R12/R14/R15/R16); only the achieved DRAM
// rate moves. R14 (best, 6.82TB/s): per-tile CTAs expose TMA-wait + setup.
// R17: persistent CTAs (grid 912, ~35 contiguous tiles each) with a 2-stage
// double-buffered smem pipeline -- TMA for tile t+1 issued before waiting on
// tile t, mbar init once per CTA, contiguous weight chunks per CTA. Keeps
// R14's proven 8-rules/256-thread tile and the evict-normal-bulk +
// discard.global.L2 scheme (weights single-use -> clean-line invalidate).

#define D_DIM 128
#define PERIOD 8
#define TILE_RULES 8
#define THREADS 256
#define GRID_CTAS 912

#define W_TILE_FLOATS (TILE_RULES * PERIOD * D_DIM)      // 8192
#define W_TILE_BYTES  (W_TILE_FLOATS * 4)                // 32768
#define IDX_TILE_BYTES (TILE_RULES * PERIOD * 8)         // 512 (int64 worst case)
#define SIDX_OFF (2 * W_TILE_BYTES)                      // 65536
#define MBAR_OFF (SIDX_OFF + 2 * IDX_TILE_BYTES)         // 66560
#define SMEM_BYTES (MBAR_OFF + 16)

__device__ int g_idx_is64;

// Detect int64 vs int32 indices: values < 2e5, so for int64 every odd 32-bit
// word is 0; for int32 odd words are random (P all-zero ~ (5e-6)^512 ~ 0).
__global__ void detect_idx_dtype(const unsigned int* __restrict__ ind_words) {
    const int lane = threadIdx.x & 31;
    unsigned int acc = 0;
    #pragma unroll
    for (int i = 0; i < 16; ++i)
        acc |= ind_words[2 * (lane * 16 + i) + 1];
    #pragma unroll
    for (int off = 16; off > 0; off >>= 1)
        acc |= __shfl_xor_sync(0xFFFFFFFFu, acc, off);
    if (lane == 0) g_idx_is64 = (acc == 0u) ? 1 : 0;
}

__global__ __launch_bounds__(THREADS) void weighted_rule_kernel(
    const float* __restrict__ lv,      // [N_SRC, 128]  random gather, wants L2 residency
    const float* __restrict__ w,       // [R, 8, 128]   bulk copy (evict-normal) + discard
    const char*  __restrict__ ind,     // [R, 8] int32 or int64 -> bulk copy
    float* __restrict__ out,           // [R, 128]
    int nrules, int ntiles, int tiles_per_cta)
{
    extern __shared__ char smem[];
    float* s_w = (float*)smem;                                    // 2 x 32 KB
    unsigned char* s_idx = (unsigned char*)(smem + SIDX_OFF);     // 2 x 512 B

    const int tid  = threadIdx.x;
    const int warp = tid >> 5;
    const int lane = tid & 31;
    const int is64 = g_idx_is64;
    const int isz  = is64 ? 8 : 4;

    const int t_begin = blockIdx.x * tiles_per_cta;
    int t_end = t_begin + tiles_per_cta;
    if (t_end > ntiles) t_end = ntiles;
    if (t_begin >= t_end) return;

    const unsigned int mbar0  = (unsigned int)__cvta_generic_to_shared(smem + MBAR_OFF);
    const unsigned int sw_a   = (unsigned int)__cvta_generic_to_shared(s_w);
    const unsigned int sidx_a = (unsigned int)__cvta_generic_to_shared(s_idx);

    if (tid == 0) {
        asm volatile("mbarrier.init.shared.b64 [%0], 1;" :: "r"(mbar0)     : "memory");
        asm volatile("mbarrier.init.shared.b64 [%0], 1;" :: "r"(mbar0 + 8) : "memory");
    }
    __syncthreads();

    // Issue TMA for tile T into buffer B (tid 0 only). Evict-normal bulk:
    // the fast stream path; L2 pollution bounded by post-consumption discard.
    #define ISSUE_TILE(T, B) do {                                                        \
        int rh_ = nrules - (T) * TILE_RULES; if (rh_ > TILE_RULES) rh_ = TILE_RULES;     \
        const unsigned int wb_ = (unsigned int)rh_ * PERIOD * D_DIM * 4;                 \
        const unsigned int ib_ = (unsigned int)rh_ * PERIOD * isz;                       \
        const unsigned int mb_ = mbar0 + (unsigned int)(B) * 8;                          \
        asm volatile("mbarrier.arrive.expect_tx.shared.b64 _, [%0], %1;"                 \
                     :: "r"(mb_), "r"(wb_ + ib_) : "memory");                            \
        asm volatile("cp.async.bulk.shared::cta.global.mbarrier::complete_tx::bytes "    \
                     "[%0], [%1], %2, [%3];"                                             \
                     :: "r"(sw_a + (unsigned int)(B) * W_TILE_BYTES),                    \
                        "l"(w + (size_t)(T) * W_TILE_FLOATS), "r"(wb_), "r"(mb_)         \
                     : "memory");                                                        \
        asm volatile("cp.async.bulk.shared::cta.global.mbarrier::complete_tx::bytes "    \
                     "[%0], [%1], %2, [%3];"                                             \
                     :: "r"(sidx_a + (unsigned int)(B) * IDX_TILE_BYTES),                \
                        "l"(ind + (size_t)(T) * TILE_RULES * PERIOD * isz),              \
                        "r"(ib_), "r"(mb_) : "memory");                                  \
    } while (0)

    if (tid == 0) ISSUE_TILE(t_begin, 0);   // prologue

    unsigned int k = 0;
    for (int t = t_begin; t < t_end; ++t, ++k) {
        const int buf = (int)(k & 1u);
        const unsigned int parity = (k >> 1) & 1u;

        // All warps done reading buffer buf^1 (iteration k-1) before refilling it.
        if (k > 0) __syncthreads();
        if (tid == 0 && t + 1 < t_end) ISSUE_TILE(t + 1, buf ^ 1);

        // Wait full (acquire) on this tile's buffer.
        {
            unsigned int done;
            asm volatile(
                "{\n\t.reg .pred p;\n\t"
                "mbarrier.try_wait.parity.acquire.cta.shared::cta.b64 p, [%1], %2;\n\t"
                "selp.b32 %0, 1, 0, p;\n\t}"
                : "=r"(done) : "r"(mbar0 + (unsigned int)buf * 8), "r"(parity) : "memory");
            if (!done) {
                asm volatile(
                    "{\n\t.reg .pred P1;\n\t"
                    "WL%=:\n\t"
                    "mbarrier.try_wait.parity.acquire.cta.shared::cta.b64 P1, [%0], %1, 0x989680;\n\t"
                    "@P1 bra.uni WD%=;\n\t"
                    "bra.uni WL%=;\n\t"
                    "WD%=:\n\t}"
                    :: "r"(mbar0 + (unsigned int)buf * 8), "r"(parity) : "memory");
            }
        }

        const int r0 = t * TILE_RULES;
        int rules_here = nrules - r0; if (rules_here > TILE_RULES) rules_here = TILE_RULES;

        // Weights consumed into smem: invalidate this tile's clean L2 lines so
        // they stop displacing layer_values (DRAM copy intact for next replay).
        {
            const unsigned int nlines = ((unsigned int)rules_here * PERIOD * D_DIM * 4) >> 7;
            if ((unsigned int)tid < nlines) {
                const char* p = (const char*)(w + (size_t)t * W_TILE_FLOATS)
                                + (unsigned int)tid * 128;
                asm volatile("discard.global.L2 [%0], 128;" :: "l"(p) : "memory");
            }
        }

        if (warp < rules_here) {
            // Indices for this warp's rule (uniform across warp -> LDS broadcast).
            int idx[PERIOD];
            if (is64) {
                const long long* ip =
                    (const long long*)(s_idx + buf * IDX_TILE_BYTES) + warp * PERIOD;
                #pragma unroll
                for (int p = 0; p < PERIOD; ++p) idx[p] = (int)ip[p];
            } else {
                const int* ip = (const int*)(s_idx + buf * IDX_TILE_BYTES) + warp * PERIOD;
                #pragma unroll
                for (int p = 0; p < PERIOD; ++p) idx[p] = ip[p];
            }

            const float4* swp =
                (const float4*)(s_w + buf * W_TILE_FLOATS + warp * PERIOD * D_DIM) + lane;

            float4 acc = make_float4(0.f, 0.f, 0.f, 0.f);
            #pragma unroll
            for (int p = 0; p < PERIOD; ++p) {
                float4 wv = swp[p * 32];                         // LDS.128, conflict-free
                const float4* xp = (const float4*)(lv + (size_t)idx[p] * D_DIM) + lane;
                float4 xv = __ldg(xp);                           // random gather
                acc.x = fmaf(wv.x, xv.x, acc.x);
                acc.y = fmaf(wv.y, xv.y, acc.y);
                acc.z = fmaf(wv.z, xv.z, acc.z);
                acc.w = fmaf(wv.w, xv.w, acc.w);
            }

            float4 res;
            res.x = tanhf(acc.x);
            res.y = tanhf(acc.y);
            res.z = tanhf(acc.z);
            res.w = tanhf(acc.w);

            // Write-once stream: evict-first store (R14 best config).
            float4* op = (float4*)(out + (size_t)(r0 + warp) * D_DIM) + lane;
            __stcs(op, res);
        }
    }
    #undef ISSUE_TILE
}

extern "C" void kernel_launch(void* const* d_in, const int* in_sizes, int n_in,
                              void* d_out, int out_size) {
    const float* lv  = (const float*)d_in[0];   // layer_values [200000,128]
    const float* w   = (const float*)d_in[1];   // weights [R,8,128]
    const char*  ind = (const char*)d_in[2];    // indices [R,8]

    const int nrules = in_sizes[2] / PERIOD;
    const int ntiles = (nrules + TILE_RULES - 1) / TILE_RULES;
    int grid = GRID_CTAS < ntiles ? GRID_CTAS : ntiles;
    const int tiles_per_cta = (ntiles + grid - 1) / grid;

    cudaFuncSetAttribute(weighted_rule_kernel,
                         cudaFuncAttributeMaxDynamicSharedMemorySize, SMEM_BYTES);

    detect_idx_dtype<<<1, 32>>>((const unsigned int*)ind);

    weighted_rule_kernel<<<grid, THREADS, SMEM_BYTES>>>(
        lv, w, ind, (float*)d_out, nrules, ntiles, tiles_per_cta);
}